// round 16
// baseline (speedup 1.0000x reference)
#include <cuda_runtime.h>
#include <cuda_fp16.h>

typedef unsigned int u32;
typedef unsigned long long ull;

#define GDIM 620
#define HH   150
#define HP   160
#define TP   64       // pairs per block (M tile)
#define NCHK 20       // 640/32
#define NT   256      // 8 warps

#define MMAX 1024
#define PMAX 50176

#define XH   40       // X/W row stride in halfs (LDSM conflict-free)

__device__ float  d_Apad[MMAX * HP];
__device__ float  d_Bpad[MMAX * HP];
__device__ float  d_distT[9 * HP];     // includes b1
__device__ float  d_genT[8 * HP];
__device__ float  d_spkT[3 * HP];
__device__ __half d_WtH[480 * 640];    // [0:160) W1c^T, [160:320) W1a^T, [320:480) W1b^T
__device__ __half d_g16[MMAX * 640];   // g fp16, row stride 640, zero padded
__device__ float  d_scores[PMAX];
__device__ int    d_starts[MMAX + 2];
__device__ int    d_ready;             // producer counter (abm blocks + tables)

__device__ __forceinline__ u32 s2u(const void* p) {
    u32 a;
    asm("{ .reg .u64 t; cvta.to.shared.u64 t, %1; cvt.u32.u64 %0, t; }" : "=r"(a) : "l"(p));
    return a;
}

#define MMA_F16(C, A, B0, B1)                                               \
    asm volatile("mma.sync.aligned.m16n8k16.row.col.f32.f16.f16.f32 "       \
        "{%0,%1,%2,%3}, {%4,%5,%6,%7}, {%8,%9}, {%0,%1,%2,%3};"             \
        : "+f"((C)[0]), "+f"((C)[1]), "+f"((C)[2]), "+f"((C)[3])            \
        : "r"((A)[0]), "r"((A)[1]), "r"((A)[2]), "r"((A)[3]),               \
          "r"(B0), "r"(B1))

#define LDSM4(R0, R1, R2, R3, ADDR)                                         \
    asm volatile("ldmatrix.sync.aligned.m8n8.x4.shared.b16 {%0,%1,%2,%3}, [%4];" \
        : "=r"(R0), "=r"(R1), "=r"(R2), "=r"(R3) : "r"(ADDR))
#define LDSM2(R0, R1, ADDR)                                                 \
    asm volatile("ldmatrix.sync.aligned.m8n8.x2.shared.b16 {%0,%1}, [%2];"  \
        : "=r"(R0), "=r"(R1) : "r"(ADDR))

#define CP16(DST, SRC)                                                      \
    asm volatile("cp.async.ca.shared.global [%0], [%1], 16;" :: "r"(DST), "l"(SRC) : "memory")
#define CP_COMMIT() asm volatile("cp.async.commit_group;" ::: "memory")
#define CP_WAIT1()  asm volatile("cp.async.wait_group 1;"  ::: "memory")

// ---- pair shared layout (bytes)
#define SM_SI   0
#define SM_SJ   256
#define SM_DB   512
#define SM_GN   768
#define SM_SP   1024
#define SM_W2   1280
#define SM_SRED 1920
#define SM_BIG  2944
#define XSOFF(b) (SM_BIG + (b) * 5120)           // X bufs: 2 x 5120
#define WSOFF(b) (SM_BIG + 10240 + (b) * 12800)  // W ring: 3 x 12800
#define SM_TOT  (SM_BIG + 10240 + 3 * 12800)     // 51584 -> 3 CTAs/SM

// ---- abm shared layout: 32-row tile, 3-stage combined ring (fits in SM_TOT)
#define ABUF    15360                  // X 2560 + W 12800
#define A_XS(b) ((b) * ABUF)
#define A_WS(b) (A_XS(b) + 2560)

// ---------------------------------------------------------------------------
// prep_k: conversions only — WtH fp16 (3 sections) and g16. Block 0 also
// resets the producer counter for this call (stream-ordered before fused_k).
// ---------------------------------------------------------------------------
__global__ void prep_k(const float* __restrict__ W1, const float* __restrict__ g,
                       int M, int nWtH) {
    int b = blockIdx.x;
    int tid = threadIdx.x;
    if (b == 0 && tid == 0) d_ready = 0;

    if (b < nWtH) {
        int e = (b * 256 + tid) * 4;
        if (e < 480 * 640) {
            int r = e / 640, k = e % 640;
            int sec = r / 160, h = r % 160;
            int base = (sec == 0) ? 2 * GDIM : ((sec == 1) ? 0 : GDIM);
            __half hv[4];
            #pragma unroll
            for (int u = 0; u < 4; u++) {
                int kk = k + u;
                float v = (h < HH && kk < GDIM) ? __ldg(&W1[(base + kk) * HH + h]) : 0.0f;
                hv[u] = __float2half(v);
            }
            *(ull*)(d_WtH + e) = *(ull*)hv;
        }
    } else {
        int e = ((b - nWtH) * 256 + tid) * 4;
        if (e < MMAX * 640) {
            int m = e / 640, k = e % 640;
            __half hv[4];
            if (m < M && k + 3 < GDIM) {
                float4 v = *(const float4*)(g + m * GDIM + k);
                hv[0] = __float2half(v.x); hv[1] = __float2half(v.y);
                hv[2] = __float2half(v.z); hv[3] = __float2half(v.w);
            } else {
                #pragma unroll
                for (int u = 0; u < 4; u++) {
                    int kk = k + u;
                    hv[u] = __float2half((m < M && kk < GDIM) ? g[m * GDIM + kk] : 0.0f);
                }
            }
            *(ull*)(d_g16 + e) = *(ull*)hv;
        }
    }
}

// ---------------------------------------------------------------------------
// fused_k: [0,nABM) abm producer blocks; nABM tables (+b1); nABM+1 starts;
// [nABM+2, +fillB) output fill; rest pair blocks (GEMM first, init+epilogue
// after spinning on d_ready == nABM+1).
// ---------------------------------------------------------------------------
__global__ __launch_bounds__(NT, 3) void fused_k(
    float* __restrict__ out, int n,
    const float* __restrict__ de,  const float* __restrict__ ge,
    const float* __restrict__ se,  const float* __restrict__ W1,
    const float* __restrict__ b1,
    const float* __restrict__ W2,  const float* __restrict__ b2,
    const float* __restrict__ ms,
    const int* __restrict__ mids,  const int* __restrict__ aids,
    const int* __restrict__ dists, const int* __restrict__ gens,
    const int* __restrict__ spks,
    int P, int M, int nABM, int fillB)
{
    extern __shared__ char smc[];
    const u32 smu = s2u(smc);
    const int tid = threadIdx.x;
    const int b   = blockIdx.x;
    const int lid = tid & 31, wi = tid >> 5;
    const int tig = lid & 3, grp = lid >> 2;
    const int target = nABM + 1;

    if (b < nABM) {
        // ================= abm producer: A/B fp16 GEMM, 32-row tile ========
        const int m0 = (b >> 1) * 32;
        const int which = b & 1;
        const int mBlk = (wi & 1) * 16, nBlk = (wi >> 1) * 40;

        const int myrow = tid >> 2, q = tid & 3;
        const char* g_src = (const char*)(d_g16 + (m0 + myrow) * 640) + q * 16;
        const char* w_src = (const char*)(d_WtH + (160 + which * 160 + tid) * 640);
        const u32 x_dst = smu + (myrow * XH + q * 8) * 2;
        const u32 w_dst = smu + 2560 + tid * (XH * 2);

        const int aRow = ((lid >> 3) & 1) * 8 + (lid & 7);
        const int aK   = (lid >> 4) * 8;
        const int bRow = (lid >> 4) * 8 + (lid & 7);
        const int bK   = ((lid >> 3) & 1) * 8;
        const int b2r  = nBlk + 32 + (lid & 7);
        const int b2k  = ((lid >> 3) & 1) * 8;

        float c[5][4];
        #pragma unroll
        for (int na = 0; na < 5; na++)
            #pragma unroll
            for (int r = 0; r < 4; r++) c[na][r] = 0.0f;

        #pragma unroll
        for (int pc = 0; pc < 2; pc++) {
            u32 off = pc * ABUF;
            if (tid < 128) CP16(x_dst + off, g_src + pc * 64);
            if (tid < HP) {
                u32 dst = w_dst + off;
                const char* src = w_src + pc * 64;
                CP16(dst, src); CP16(dst + 16, src + 16);
                CP16(dst + 32, src + 32); CP16(dst + 48, src + 48);
            }
            CP_COMMIT();
        }

        int buf = 0;
        for (int cch = 0; cch < NCHK; cch++) {
            CP_WAIT1();
            __syncthreads();
            if (cch + 2 < NCHK) {
                int nb = buf + 2; if (nb >= 3) nb -= 3;
                u32 off = nb * ABUF;
                if (tid < 128) CP16(x_dst + off, g_src + (cch + 2) * 64);
                if (tid < HP) {
                    u32 dst = w_dst + off;
                    const char* src = w_src + (cch + 2) * 64;
                    CP16(dst, src); CP16(dst + 16, src + 16);
                    CP16(dst + 32, src + 32); CP16(dst + 48, src + 48);
                }
            }
            CP_COMMIT();

            const u32 xb = smu + A_XS(buf);
            const u32 wb = smu + A_WS(buf);
            #pragma unroll
            for (int s = 0; s < 2; s++) {
                u32 a[4];
                u32 ad = xb + ((mBlk + aRow) * XH + s * 16 + aK) * 2;
                LDSM4(a[0], a[1], a[2], a[3], ad);
                #pragma unroll
                for (int ng = 0; ng < 2; ng++) {
                    u32 bd = wb + ((nBlk + ng * 16 + bRow) * XH + s * 16 + bK) * 2;
                    u32 b0, b1v, b2v, b3;
                    LDSM4(b0, b1v, b2v, b3, bd);
                    MMA_F16(c[2*ng],     a, b0, b1v);
                    MMA_F16(c[2*ng + 1], a, b2v, b3);
                }
                {
                    u32 bd = wb + (b2r * XH + s * 16 + b2k) * 2;
                    u32 b0, b1v;
                    LDSM2(b0, b1v, bd);
                    MMA_F16(c[4], a, b0, b1v);
                }
            }
            if (++buf == 3) buf = 0;
        }

        float* dst = which ? d_Bpad : d_Apad;
        {
            int r = m0 + mBlk + grp;
            #pragma unroll
            for (int na = 0; na < 5; na++) {
                int col = nBlk + na * 8 + 2 * tig;
                if (r < M)     *(float2*)&dst[r * HP + col]       = make_float2(c[na][0], c[na][1]);
                if (r + 8 < M) *(float2*)&dst[(r + 8) * HP + col] = make_float2(c[na][2], c[na][3]);
            }
        }
        __syncthreads();
        if (tid == 0) { __threadfence(); atomicAdd(&d_ready, 1); }

    } else if (b == nABM) {
        // ================= phi tables (+b1 folded into distT) ==============
        for (int e = tid; e < 20 * HP; e += blockDim.x) {
            int row = e / HP, h = e % HP;
            const float* emb; int dbase; float* dst; float acc;
            if (row < 9)       { emb = de + row * 20;        dbase = 3 * GDIM;      dst = d_distT + row * HP + h;        acc = (h < HH) ? b1[h] : 0.0f; }
            else if (row < 17) { emb = ge + (row - 9) * 20;  dbase = 3 * GDIM + 20; dst = d_genT  + (row - 9) * HP + h;  acc = 0.0f; }
            else               { emb = se + (row - 17) * 20; dbase = 3 * GDIM + 40; dst = d_spkT  + (row - 17) * HP + h; acc = 0.0f; }
            if (h < HH) {
                #pragma unroll
                for (int k = 0; k < 20; k++) acc += emb[k] * W1[(dbase + k) * HH + h];
            }
            *dst = acc;
        }
        __syncthreads();
        if (tid == 0) { __threadfence(); atomicAdd(&d_ready, 1); }

    } else if (b == nABM + 1) {
        // ================= segment starts (softmax dep only) ===============
        for (int m = tid; m <= M; m += blockDim.x) {
            int lo = 0, hi = P;
            while (lo < hi) {
                int mid = (lo + hi) >> 1;
                if (mids[mid] < m) lo = mid + 1; else hi = mid;
            }
            d_starts[m] = lo;
        }
    } else if (b < nABM + 2 + fillB) {
        // ================= output fill =====================================
        int e = ((b - nABM - 2) * 256 + tid) * 4;
        if (e + 3 < n) {
            float4 v = make_float4(1000.0f, 1000.0f, 1000.0f, 1000.0f);
            if (e == 0) v.x = 1.0f;
            *(float4*)(out + e) = v;
        } else {
            for (int u = 0; u < 4 && e + u < n; u++)
                out[e + u] = (e + u == 0) ? 1.0f : 1000.0f;
        }
    } else {
        // ================= pair block: GEMM then init+epilogue =============
        int*   s_si = (int*)(smc + SM_SI);
        int*   s_sj = (int*)(smc + SM_SJ);
        int*   s_db = (int*)(smc + SM_DB);
        int*   s_gn = (int*)(smc + SM_GN);
        int*   s_sp = (int*)(smc + SM_SP);
        float* w2s  = (float*)(smc + SM_W2);
        float* sred = (float*)(smc + SM_SRED);

        const int pb = (b - nABM - 2 - fillB) * TP;

        if (tid < TP) {
            int p = pb + tid;
            bool ok = p < P;
            s_si[tid] = ok ? mids[p] : 0;
            s_sj[tid] = ok ? aids[p] : 0;
            int dd = ok ? dists[p] : 0;
            s_db[tid] = (dd >= 1) + (dd >= 2) + (dd >= 3) + (dd >= 4) +
                        (dd >= 8) + (dd >= 16) + (dd >= 32) + (dd >= 64);
            s_gn[tid] = ok ? gens[p] : 0;
            s_sp[tid] = ok ? spks[p] : 0;
        }
        if (tid < HP) w2s[tid] = (tid < HH) ? W2[tid] : 0.0f;
        __syncthreads();

        const int mBlk = (wi & 1) * 32, nBlk = (wi >> 1) * 40;

        float c[2][5][4];
        #pragma unroll
        for (int ma = 0; ma < 2; ma++)
            #pragma unroll
            for (int na = 0; na < 5; na++)
                #pragma unroll
                for (int r = 0; r < 4; r++) c[ma][na][r] = 0.0f;

        const int myrow = tid >> 2, q = tid & 3;
        const uint4* gi16 = (const uint4*)(d_g16 + s_si[myrow] * 640) + q;
        const uint4* gj16 = (const uint4*)(d_g16 + s_sj[myrow] * 640) + q;
        const char*  wsrc = (const char*)d_WtH + tid * 1280;

        const int aRow = ((lid >> 3) & 1) * 8 + (lid & 7);
        const int aK   = (lid >> 4) * 8;
        const int bRow = (lid >> 4) * 8 + (lid & 7);
        const int bK   = ((lid >> 3) & 1) * 8;
        const int b2r  = nBlk + 32 + (lid & 7);
        const int b2k  = ((lid >> 3) & 1) * 8;

        uint4 xi = __ldg(gi16);
        uint4 xj = __ldg(gj16);

        #pragma unroll
        for (int pc = 0; pc < 2; pc++) {
            if (tid < HP) {
                u32 dst = smu + WSOFF(pc) + tid * (XH * 2);
                const char* src = wsrc + pc * 64;
                CP16(dst, src); CP16(dst + 16, src + 16);
                CP16(dst + 32, src + 32); CP16(dst + 48, src + 48);
            }
            CP_COMMIT();
        }

        int wbuf = 0;
        for (int cch = 0; cch < NCHK; cch++) {
            const int xbuf = cch & 1;
            {
                const __half2* a2 = (const __half2*)&xi;
                const __half2* b2h = (const __half2*)&xj;
                uint4 st;
                __half2* o2 = (__half2*)&st;
                #pragma unroll
                for (int k = 0; k < 4; k++) o2[k] = __hmul2(a2[k], b2h[k]);
                *((uint4*)(smc + XSOFF(xbuf)) + myrow * 5 + q) = st;
            }
            CP_WAIT1();
            __syncthreads();

            if (cch + 2 < NCHK) {
                int nb = wbuf + 2; if (nb >= 3) nb -= 3;
                if (tid < HP) {
                    u32 dst = smu + WSOFF(nb) + tid * (XH * 2);
                    const char* src = wsrc + (cch + 2) * 64;
                    CP16(dst, src); CP16(dst + 16, src + 16);
                    CP16(dst + 32, src + 32); CP16(dst + 48, src + 48);
                }
            }
            CP_COMMIT();
            if (cch + 1 < NCHK) {
                xi = __ldg(gi16 + (cch + 1) * 4);
                xj = __ldg(gj16 + (cch + 1) * 4);
            }

            const u32 xb = smu + XSOFF(xbuf);
            const u32 wb = smu + WSOFF(wbuf);
            #pragma unroll
            for (int s = 0; s < 2; s++) {
                u32 a[2][4];
                #pragma unroll
                for (int ma = 0; ma < 2; ma++) {
                    u32 ad = xb + ((mBlk + ma * 16 + aRow) * XH + s * 16 + aK) * 2;
                    LDSM4(a[ma][0], a[ma][1], a[ma][2], a[ma][3], ad);
                }
                #pragma unroll
                for (int ng = 0; ng < 2; ng++) {
                    u32 ad = wb + ((nBlk + ng * 16 + bRow) * XH + s * 16 + bK) * 2;
                    u32 b0, b1v, b2v, b3;
                    LDSM4(b0, b1v, b2v, b3, ad);
                    MMA_F16(c[0][2*ng],     a[0], b0, b1v);
                    MMA_F16(c[1][2*ng],     a[1], b0, b1v);
                    MMA_F16(c[0][2*ng + 1], a[0], b2v, b3);
                    MMA_F16(c[1][2*ng + 1], a[1], b2v, b3);
                }
                {
                    u32 ad = wb + (b2r * XH + s * 16 + b2k) * 2;
                    u32 b0, b1v;
                    LDSM2(b0, b1v, ad);
                    MMA_F16(c[0][4], a[0], b0, b1v);
                    MMA_F16(c[1][4], a[1], b0, b1v);
                }
            }
            if (++wbuf == 3) wbuf = 0;
        }

        // ---- wait for producers (abm blocks + tables), then add init terms
        if (tid == 0) {
            while (*(volatile int*)&d_ready < target) { }
            __threadfence();
        }
        __syncthreads();

        #pragma unroll
        for (int ma = 0; ma < 2; ma++)
            #pragma unroll
            for (int rr = 0; rr < 2; rr++) {
                int r = mBlk + ma * 16 + grp + 8 * rr;
                const float2* Ap = (const float2*)&d_Apad[s_si[r] * HP];
                const float2* Bp = (const float2*)&d_Bpad[s_sj[r] * HP];
                const float2* Dp = (const float2*)&d_distT[s_db[r] * HP];
                const float2* Gp = (const float2*)&d_genT[s_gn[r] * HP];
                const float2* Sp = (const float2*)&d_spkT[s_sp[r] * HP];
                #pragma unroll
                for (int na = 0; na < 5; na++) {
                    int c2 = ((nBlk + na * 8) >> 1) + tig;
                    float2 a = Ap[c2];
                    float2 bb = Bp[c2];
                    float2 d = Dp[c2];
                    float2 g2 = Gp[c2];
                    float2 s2 = Sp[c2];
                    c[ma][na][2 * rr]     += a.x + bb.x + d.x + g2.x + s2.x;
                    c[ma][na][2 * rr + 1] += a.y + bb.y + d.y + g2.y + s2.y;
                }
            }

        // ---- epilogue: relu + dot W2, reduce over tig, combine 4 n-blocks
        float part[2][2] = {{0.f, 0.f}, {0.f, 0.f}};
        #pragma unroll
        for (int ma = 0; ma < 2; ma++)
            #pragma unroll
            for (int na = 0; na < 5; na++) {
                int col = nBlk + na * 8 + 2 * tig;
                float w0 = w2s[col], w1 = w2s[col + 1];
                float v0 = fmaxf(c[ma][na][0], 0.f), v1 = fmaxf(c[ma][na][1], 0.f);
                float v2 = fmaxf(c[ma][na][2], 0.f), v3 = fmaxf(c[ma][na][3], 0.f);
                part[ma][0] += v0 * w0 + v1 * w1;
                part[ma][1] += v2 * w0 + v3 * w1;
            }
        #pragma unroll
        for (int ma = 0; ma < 2; ma++)
            #pragma unroll
            for (int rr = 0; rr < 2; rr++) {
                float v = part[ma][rr];
                v += __shfl_xor_sync(0xffffffffu, v, 1);
                v += __shfl_xor_sync(0xffffffffu, v, 2);
                part[ma][rr] = v;
            }
        if (tig == 0) {
            int nb = wi >> 1;
            #pragma unroll
            for (int ma = 0; ma < 2; ma++)
                #pragma unroll
                for (int rr = 0; rr < 2; rr++) {
                    int row = mBlk + ma * 16 + grp + 8 * rr;
                    sred[row * 4 + nb] = part[ma][rr];
                }
        }
        __syncthreads();
        if (tid < TP) {
            int p = pb + tid;
            if (p < P) {
                float s = sred[tid * 4] + sred[tid * 4 + 1] +
                          sred[tid * 4 + 2] + sred[tid * 4 + 3];
                d_scores[p] = s + __ldg(b2) + ms[s_si[tid]] + ms[s_sj[tid]];
            }
        }
    }
}

// ---------------------------------------------------------------------------
// Ragged softmax (+epsilon logit 0), one warp per mention
// ---------------------------------------------------------------------------
__global__ void softmax_k(float* __restrict__ out, int M) {
    int warp = (blockIdx.x * blockDim.x + threadIdx.x) >> 5;
    int lane = threadIdx.x & 31;
    if (warp >= M) return;
    int s0 = d_starts[warp], s1 = d_starts[warp + 1];
    int n = s1 - s0;

    float mx = 0.0f;
    for (int i = lane; i < n; i += 32) mx = fmaxf(mx, d_scores[s0 + i]);
    #pragma unroll
    for (int off = 16; off; off >>= 1) mx = fmaxf(mx, __shfl_xor_sync(0xffffffffu, mx, off));

    float sum = 0.0f;
    for (int i = lane; i < n; i += 32) sum += expf(d_scores[s0 + i] - mx);
    #pragma unroll
    for (int off = 16; off; off >>= 1) sum += __shfl_xor_sync(0xffffffffu, sum, off);

    float eps = expf(-mx);
    float inv = 1.0f / (sum + eps);
    float* row = out + (warp + 1) * 161;
    for (int i = lane; i < n; i += 32) row[i] = expf(d_scores[s0 + i] - mx) * inv;
    if (lane == 0) row[n] = eps * inv;
}

// ---------------------------------------------------------------------------
extern "C" void kernel_launch(void* const* d_in, const int* in_sizes, int n_in,
                              void* d_out, int out_size) {
    const float* g_i   = (const float*)d_in[0];
    const float* msc   = (const float*)d_in[1];
    const float* de    = (const float*)d_in[2];
    const float* ge    = (const float*)d_in[3];
    const float* se    = (const float*)d_in[4];
    const float* W1    = (const float*)d_in[5];
    const float* b1    = (const float*)d_in[6];
    const float* W2    = (const float*)d_in[7];
    const float* b2    = (const float*)d_in[8];
    const int*   mids  = (const int*)d_in[9];
    const int*   aids  = (const int*)d_in[10];
    const int*   dists = (const int*)d_in[11];
    const int*   gens  = (const int*)d_in[12];
    const int*   spks  = (const int*)d_in[13];

    int M = in_sizes[1];
    int P = in_sizes[9];
    float* out = (float*)d_out;

    int nWtH  = (480 * 640 / 4 + 255) / 256;    // 300
    int nG16  = (MMAX * 640 / 4 + 255) / 256;   // 640
    int nABM  = 2 * ((M + 31) / 32);            // 64
    int fillB = ((out_size + 3) / 4 + 255) / 256;
    int nPair = (P + TP - 1) / TP;

    cudaFuncSetAttribute(fused_k, cudaFuncAttributeMaxDynamicSharedMemorySize, SM_TOT);

    prep_k<<<nWtH + nG16, 256>>>(W1, g_i, M, nWtH);
    fused_k<<<nABM + 2 + fillB + nPair, NT, SM_TOT>>>(
        out, out_size, de, ge, se, W1, b1, W2, b2, msc,
        mids, aids, dists, gens, spks, P, M, nABM, fillB);
    softmax_k<<<(M + 7) / 8, 256>>>(out, M);
}

// round 17
// speedup vs baseline: 1.1373x; 1.1373x over previous
#include <cuda_runtime.h>
#include <cuda_fp16.h>

typedef unsigned int u32;
typedef unsigned long long ull;

#define GDIM 620
#define HH   150
#define HP   160
#define TP   64       // pairs per block (M tile)
#define NCHK 20       // 640/32
#define NT   256      // 8 warps: 2 m-blocks x 4 n-blocks

#define MMAX 1024
#define PMAX 50176

#define XH   40       // Xs/Ws row stride in halfs (LDSM conflict-free)
#define CST  168      // Ci row stride in floats

__device__ float  d_Apad[MMAX * HP];
__device__ float  d_Bpad[MMAX * HP];
__device__ float  d_distT[9 * HP];     // includes b1
__device__ float  d_genT[8 * HP];
__device__ float  d_spkT[3 * HP];
__device__ __half d_WtH[480 * 640];    // [0:160) W1c^T, [160:320) W1a^T, [320:480) W1b^T
__device__ __half d_g16[MMAX * 640];   // g fp16, row stride 640, zero padded
__device__ float  d_scores[PMAX];
__device__ int    d_starts[MMAX + 2];

__device__ __forceinline__ u32 s2u(const void* p) {
    u32 a;
    asm("{ .reg .u64 t; cvta.to.shared.u64 t, %1; cvt.u32.u64 %0, t; }" : "=r"(a) : "l"(p));
    return a;
}

#define MMA_F16(C, A, B0, B1)                                               \
    asm volatile("mma.sync.aligned.m16n8k16.row.col.f32.f16.f16.f32 "       \
        "{%0,%1,%2,%3}, {%4,%5,%6,%7}, {%8,%9}, {%0,%1,%2,%3};"             \
        : "+f"((C)[0]), "+f"((C)[1]), "+f"((C)[2]), "+f"((C)[3])            \
        : "r"((A)[0]), "r"((A)[1]), "r"((A)[2]), "r"((A)[3]),               \
          "r"(B0), "r"(B1))

#define LDSM4(R0, R1, R2, R3, ADDR)                                         \
    asm volatile("ldmatrix.sync.aligned.m8n8.x4.shared.b16 {%0,%1,%2,%3}, [%4];" \
        : "=r"(R0), "=r"(R1), "=r"(R2), "=r"(R3) : "r"(ADDR))
#define LDSM2(R0, R1, ADDR)                                                 \
    asm volatile("ldmatrix.sync.aligned.m8n8.x2.shared.b16 {%0,%1}, [%2];"  \
        : "=r"(R0), "=r"(R1) : "r"(ADDR))

#define CP16(DST, SRC)                                                      \
    asm volatile("cp.async.ca.shared.global [%0], [%1], 16;" :: "r"(DST), "l"(SRC) : "memory")
#define CP_COMMIT() asm volatile("cp.async.commit_group;" ::: "memory")
#define CP_WAIT1()  asm volatile("cp.async.wait_group 1;"  ::: "memory")

// ---- pair_k shared layout (bytes). Ci (init) aliases X/W buffers (mainloop)
#define SM_SI   0
#define SM_SJ   256
#define SM_DB   512
#define SM_GN   768
#define SM_SP   1024
#define SM_W2   1280
#define SM_SRED 1920
#define SM_BIG  2944
#define CI_BYTES (TP * CST * 4)           // 43008
#define XSOFF(b) (SM_BIG + (b) * 5120)    // X bufs: 2 x 5120
#define WSOFF(b) (SM_BIG + 10240 + (b) * 12800)  // W ring: 3 x 12800
#define SM_TOT  (SM_BIG + 10240 + 3 * 12800)     // 51584 -> 3 CTAs/SM

// ---- abm_k shared layout: 3-stage combined ring (X 5120 + W 12800)
#define A_XS(b) ((b) * 17920)
#define A_WS(b) (A_XS(b) + 5120)
#define ABM_TOT (3 * 17920)               // 53760

// ---------------------------------------------------------------------------
// prep_k: [0,nWtH) WtH fp16 (3 sections), [nWtH,+nG16) g16, then tables,
// starts, output fill. All independent.
// ---------------------------------------------------------------------------
__global__ void prep_k(float* __restrict__ out, int n,
                       const float* __restrict__ de, const float* __restrict__ ge,
                       const float* __restrict__ se, const float* __restrict__ W1,
                       const float* __restrict__ b1, const float* __restrict__ g,
                       const int* __restrict__ mids, int P, int M,
                       int nWtH, int nG16) {
    int b = blockIdx.x;
    int tid = threadIdx.x;

    if (b < nWtH) {
        int e = (b * 256 + tid) * 4;
        if (e < 480 * 640) {
            int r = e / 640, k = e % 640;
            int sec = r / 160, h = r % 160;
            int base = (sec == 0) ? 2 * GDIM : ((sec == 1) ? 0 : GDIM);
            __half hv[4];
            #pragma unroll
            for (int u = 0; u < 4; u++) {
                int kk = k + u;
                float v = (h < HH && kk < GDIM) ? __ldg(&W1[(base + kk) * HH + h]) : 0.0f;
                hv[u] = __float2half(v);
            }
            *(ull*)(d_WtH + e) = *(ull*)hv;
        }
    } else if (b < nWtH + nG16) {
        int e = ((b - nWtH) * 256 + tid) * 4;
        if (e < M * 640) {
            int m = e / 640, k = e % 640;
            __half hv[4];
            if (k + 3 < GDIM) {
                float4 v = *(const float4*)(g + m * GDIM + k);
                hv[0] = __float2half(v.x); hv[1] = __float2half(v.y);
                hv[2] = __float2half(v.z); hv[3] = __float2half(v.w);
            } else {
                #pragma unroll
                for (int u = 0; u < 4; u++) {
                    int kk = k + u;
                    hv[u] = __float2half((kk < GDIM) ? g[m * GDIM + kk] : 0.0f);
                }
            }
            *(ull*)(d_g16 + e) = *(ull*)hv;
        }
    } else if (b == nWtH + nG16) {
        for (int e = tid; e < 20 * HP; e += blockDim.x) {
            int row = e / HP, h = e % HP;
            const float* emb; int dbase; float* dst; float acc;
            if (row < 9)       { emb = de + row * 20;        dbase = 3 * GDIM;      dst = d_distT + row * HP + h;        acc = (h < HH) ? b1[h] : 0.0f; }
            else if (row < 17) { emb = ge + (row - 9) * 20;  dbase = 3 * GDIM + 20; dst = d_genT  + (row - 9) * HP + h;  acc = 0.0f; }
            else               { emb = se + (row - 17) * 20; dbase = 3 * GDIM + 40; dst = d_spkT  + (row - 17) * HP + h; acc = 0.0f; }
            if (h < HH) {
                #pragma unroll
                for (int k = 0; k < 20; k++) acc += emb[k] * W1[(dbase + k) * HH + h];
            }
            *dst = acc;
        }
    } else if (b == nWtH + nG16 + 1) {
        for (int m = tid; m <= M; m += blockDim.x) {
            int lo = 0, hi = P;
            while (lo < hi) {
                int mid = (lo + hi) >> 1;
                if (mids[mid] < m) lo = mid + 1; else hi = mid;
            }
            d_starts[m] = lo;
        }
    } else {
        int e = ((b - nWtH - nG16 - 2) * 256 + tid) * 4;
        if (e + 3 < n) {
            float4 v = make_float4(1000.0f, 1000.0f, 1000.0f, 1000.0f);
            if (e == 0) v.x = 1.0f;
            *(float4*)(out + e) = v;
        } else {
            for (int u = 0; u < 4 && e + u < n; u++)
                out[e + u] = (e + u == 0) ? 1.0f : 1000.0f;
        }
    }
}

// ---------------------------------------------------------------------------
// abm_k: A/B precompute as fp16 tensor GEMM, 3-stage cp.async ring.
// grid (M/64, 2): y=0 -> Apad (W1a), y=1 -> Bpad (W1b).
// ---------------------------------------------------------------------------
__global__ __launch_bounds__(NT) void abm_k(int M) {
    extern __shared__ char smc[];
    const u32 smu = s2u(smc);
    const int tid = threadIdx.x;
    const int m0 = blockIdx.x * 64;
    const int which = blockIdx.y;

    const int lid = tid & 31, wi = tid >> 5;
    const int mBlk = (wi & 1) * 32, nBlk = (wi >> 1) * 40;
    const int tig = lid & 3, grp = lid >> 2;

    const int myrow = tid >> 2, q = tid & 3;
    const char* g_src = (const char*)(d_g16 + (m0 + myrow) * 640) + q * 16;
    const char* w_src = (const char*)(d_WtH + (160 + which * 160 + tid) * 640);
    const u32 x_dst = smu + (myrow * XH + q * 8) * 2;
    const u32 w_dst = smu + 5120 + tid * (XH * 2);

    const int aRow = ((lid >> 3) & 1) * 8 + (lid & 7);
    const int aK   = (lid >> 4) * 8;
    const int bRow = (lid >> 4) * 8 + (lid & 7);
    const int bK   = ((lid >> 3) & 1) * 8;
    const int b2r  = nBlk + 32 + (lid & 7);
    const int b2k  = ((lid >> 3) & 1) * 8;

    float c[2][5][4];
    #pragma unroll
    for (int ma = 0; ma < 2; ma++)
        #pragma unroll
        for (int na = 0; na < 5; na++)
            #pragma unroll
            for (int r = 0; r < 4; r++) c[ma][na][r] = 0.0f;

    // prologue: chunks 0 and 1
    #pragma unroll
    for (int pc = 0; pc < 2; pc++) {
        u32 off = pc * 17920;
        CP16(x_dst + off, g_src + pc * 64);
        if (tid < HP) {
            u32 dst = w_dst + off;
            const char* src = w_src + pc * 64;
            CP16(dst, src); CP16(dst + 16, src + 16);
            CP16(dst + 32, src + 32); CP16(dst + 48, src + 48);
        }
        CP_COMMIT();
    }

    int buf = 0;
    for (int cch = 0; cch < NCHK; cch++) {
        CP_WAIT1();
        __syncthreads();

        if (cch + 2 < NCHK) {
            int nb = buf + 2; if (nb >= 3) nb -= 3;
            u32 off = nb * 17920;
            CP16(x_dst + off, g_src + (cch + 2) * 64);
            if (tid < HP) {
                u32 dst = w_dst + off;
                const char* src = w_src + (cch + 2) * 64;
                CP16(dst, src); CP16(dst + 16, src + 16);
                CP16(dst + 32, src + 32); CP16(dst + 48, src + 48);
            }
        }
        CP_COMMIT();

        const u32 xb = smu + A_XS(buf);
        const u32 wb = smu + A_WS(buf);
        #pragma unroll
        for (int s = 0; s < 2; s++) {
            u32 a[2][4];
            #pragma unroll
            for (int ma = 0; ma < 2; ma++) {
                u32 ad = xb + ((mBlk + ma * 16 + aRow) * XH + s * 16 + aK) * 2;
                LDSM4(a[ma][0], a[ma][1], a[ma][2], a[ma][3], ad);
            }
            #pragma unroll
            for (int ng = 0; ng < 2; ng++) {
                u32 bd = wb + ((nBlk + ng * 16 + bRow) * XH + s * 16 + bK) * 2;
                u32 b0, b1, b2v, b3;
                LDSM4(b0, b1, b2v, b3, bd);
                MMA_F16(c[0][2*ng],     a[0], b0, b1);
                MMA_F16(c[1][2*ng],     a[1], b0, b1);
                MMA_F16(c[0][2*ng + 1], a[0], b2v, b3);
                MMA_F16(c[1][2*ng + 1], a[1], b2v, b3);
            }
            {
                u32 bd = wb + (b2r * XH + s * 16 + b2k) * 2;
                u32 b0, b1;
                LDSM2(b0, b1, bd);
                MMA_F16(c[0][4], a[0], b0, b1);
                MMA_F16(c[1][4], a[1], b0, b1);
            }
        }
        if (++buf == 3) buf = 0;
    }

    float* dst = which ? d_Bpad : d_Apad;
    #pragma unroll
    for (int ma = 0; ma < 2; ma++) {
        int r = m0 + mBlk + ma * 16 + grp;
        #pragma unroll
        for (int na = 0; na < 5; na++) {
            int col = nBlk + na * 8 + 2 * tig;
            if (r < M)     *(float2*)&dst[r * HP + col]       = make_float2(c[ma][na][0], c[ma][na][1]);
            if (r + 8 < M) *(float2*)&dst[(r + 8) * HP + col] = make_float2(c[ma][na][2], c[ma][na][3]);
        }
    }
}

// ---------------------------------------------------------------------------
// pair_k: 64 pairs x 160 h, 8 warps = 2m x 4n. Exact fp32 C init (Ci staging);
// fp16 m16n8k16 Hadamard GEMM. X reg-prefetch (2 bufs, loads HOISTED before
// the wait for full-chunk latency cover) + W 3-stage cp.async ring. 3 CTAs/SM.
// ---------------------------------------------------------------------------
__global__ __launch_bounds__(NT, 3) void pair_k(
    const float* __restrict__ W2,  const float* __restrict__ b2,
    const float* __restrict__ ms,
    const int* __restrict__ mids,  const int* __restrict__ aids,
    const int* __restrict__ dists, const int* __restrict__ gens,
    const int* __restrict__ spks,  int P)
{
    extern __shared__ char smc[];
    int*   s_si = (int*)(smc + SM_SI);
    int*   s_sj = (int*)(smc + SM_SJ);
    int*   s_db = (int*)(smc + SM_DB);
    int*   s_gn = (int*)(smc + SM_GN);
    int*   s_sp = (int*)(smc + SM_SP);
    float* w2s  = (float*)(smc + SM_W2);
    float* sred = (float*)(smc + SM_SRED);
    float* Ci   = (float*)(smc + SM_BIG);

    const u32 smu = s2u(smc);
    const int tid = threadIdx.x;
    const int pb  = blockIdx.x * TP;

    if (tid < TP) {
        int p = pb + tid;
        bool ok = p < P;
        s_si[tid] = ok ? mids[p] : 0;
        s_sj[tid] = ok ? aids[p] : 0;
        int dd = ok ? dists[p] : 0;
        s_db[tid] = (dd >= 1) + (dd >= 2) + (dd >= 3) + (dd >= 4) +
                    (dd >= 8) + (dd >= 16) + (dd >= 32) + (dd >= 64);
        s_gn[tid] = ok ? gens[p] : 0;
        s_sp[tid] = ok ? spks[p] : 0;
    }
    if (tid < HP) w2s[tid] = (tid < HH) ? W2[tid] : 0.0f;
    __syncthreads();

    // ---- stage exact init tile Ci[64][160] (fp32)
    {
        const float4* A4 = (const float4*)d_Apad;
        const float4* B4 = (const float4*)d_Bpad;
        const float4* D4 = (const float4*)d_distT;
        const float4* G4 = (const float4*)d_genT;
        const float4* S4 = (const float4*)d_spkT;
        #pragma unroll
        for (int it = 0; it < (TP * 40) / NT; it++) {
            int e = tid + NT * it;
            int row = e / 40, c4 = e % 40;
            float4 a = __ldg(&A4[s_si[row] * 40 + c4]);
            float4 b = __ldg(&B4[s_sj[row] * 40 + c4]);
            float4 d = __ldg(&D4[s_db[row] * 40 + c4]);
            float4 gg = __ldg(&G4[s_gn[row] * 40 + c4]);
            float4 s = __ldg(&S4[s_sp[row] * 40 + c4]);
            float4 v = make_float4(a.x+b.x+d.x+gg.x+s.x, a.y+b.y+d.y+gg.y+s.y,
                                   a.z+b.z+d.z+gg.z+s.z, a.w+b.w+d.w+gg.w+s.w);
            *(float4*)(Ci + row * CST + c4 * 4) = v;
        }
    }
    __syncthreads();

    const int lid = tid & 31, wi = tid >> 5;
    const int mBlk = (wi & 1) * 32, nBlk = (wi >> 1) * 40;
    const int tig = lid & 3, grp = lid >> 2;

    // ---- load C fragments from Ci
    float c[2][5][4];
    #pragma unroll
    for (int ma = 0; ma < 2; ma++) {
        int r = mBlk + ma * 16 + grp;
        #pragma unroll
        for (int na = 0; na < 5; na++) {
            int col = nBlk + na * 8 + 2 * tig;
            float2 lo = *(const float2*)(Ci + r * CST + col);
            float2 hi = *(const float2*)(Ci + (r + 8) * CST + col);
            c[ma][na][0] = lo.x; c[ma][na][1] = lo.y;
            c[ma][na][2] = hi.x; c[ma][na][3] = hi.y;
        }
    }

    const int myrow = tid >> 2, q = tid & 3;
    const uint4* gi16 = (const uint4*)(d_g16 + s_si[myrow] * 640) + q;
    const uint4* gj16 = (const uint4*)(d_g16 + s_sj[myrow] * 640) + q;
    const char*  wsrc = (const char*)d_WtH + tid * 1280;

    const int aRow = ((lid >> 3) & 1) * 8 + (lid & 7);
    const int aK   = (lid >> 4) * 8;
    const int bRow = (lid >> 4) * 8 + (lid & 7);
    const int bK   = ((lid >> 3) & 1) * 8;
    const int b2r  = nBlk + 32 + (lid & 7);
    const int b2k  = ((lid >> 3) & 1) * 8;

    uint4 xi, xj;
    xi = __ldg(gi16);
    xj = __ldg(gj16);
    __syncthreads();   // Ci fragment reads done; X/W region reusable

    // W ring prologue: chunks 0 and 1
    #pragma unroll
    for (int pc = 0; pc < 2; pc++) {
        if (tid < HP) {
            u32 dst = smu + WSOFF(pc) + tid * (XH * 2);
            const char* src = wsrc + pc * 64;
            CP16(dst, src); CP16(dst + 16, src + 16);
            CP16(dst + 32, src + 32); CP16(dst + 48, src + 48);
        }
        CP_COMMIT();
    }

    int wbuf = 0;
    for (int cch = 0; cch < NCHK; cch++) {
        const int xbuf = cch & 1;
        // store prefetched X chunk: 4 x hmul2 -> 16B
        {
            const __half2* a2 = (const __half2*)&xi;
            const __half2* b2h = (const __half2*)&xj;
            uint4 st;
            __half2* o2 = (__half2*)&st;
            #pragma unroll
            for (int k = 0; k < 4; k++) o2[k] = __hmul2(a2[k], b2h[k]);
            *((uint4*)(smc + XSOFF(xbuf)) + myrow * 5 + q) = st;
        }
        // HOISTED: issue next-chunk X loads before the wait (full-chunk cover)
        if (cch + 1 < NCHK) {
            xi = __ldg(gi16 + (cch + 1) * 4);
            xj = __ldg(gj16 + (cch + 1) * 4);
        }
        CP_WAIT1();          // W chunk cch landed (cch+1 may fly)
        __syncthreads();

        if (cch + 2 < NCHK) {
            int nb = wbuf + 2; if (nb >= 3) nb -= 3;
            if (tid < HP) {
                u32 dst = smu + WSOFF(nb) + tid * (XH * 2);
                const char* src = wsrc + (cch + 2) * 64;
                CP16(dst, src); CP16(dst + 16, src + 16);
                CP16(dst + 32, src + 32); CP16(dst + 48, src + 48);
            }
        }
        CP_COMMIT();

        const u32 xb = smu + XSOFF(xbuf);
        const u32 wb = smu + WSOFF(wbuf);
        #pragma unroll
        for (int s = 0; s < 2; s++) {
            u32 a[2][4];
            #pragma unroll
            for (int ma = 0; ma < 2; ma++) {
                u32 ad = xb + ((mBlk + ma * 16 + aRow) * XH + s * 16 + aK) * 2;
                LDSM4(a[ma][0], a[ma][1], a[ma][2], a[ma][3], ad);
            }
            #pragma unroll
            for (int ng = 0; ng < 2; ng++) {
                u32 ad = wb + ((nBlk + ng * 16 + bRow) * XH + s * 16 + bK) * 2;
                u32 b0, b1, b2v, b3;
                LDSM4(b0, b1, b2v, b3, ad);
                MMA_F16(c[0][2*ng],     a[0], b0, b1);
                MMA_F16(c[1][2*ng],     a[1], b0, b1);
                MMA_F16(c[0][2*ng + 1], a[0], b2v, b3);
                MMA_F16(c[1][2*ng + 1], a[1], b2v, b3);
            }
            {
                u32 ad = wb + (b2r * XH + s * 16 + b2k) * 2;
                u32 b0, b1;
                LDSM2(b0, b1, ad);
                MMA_F16(c[0][4], a[0], b0, b1);
                MMA_F16(c[1][4], a[1], b0, b1);
            }
        }
        if (++wbuf == 3) wbuf = 0;
    }

    // ---- epilogue: relu + dot W2, reduce over tig, combine 4 n-blocks
    float part[2][2] = {{0.f, 0.f}, {0.f, 0.f}};
    #pragma unroll
    for (int ma = 0; ma < 2; ma++)
        #pragma unroll
        for (int na = 0; na < 5; na++) {
            int col = nBlk + na * 8 + 2 * tig;
            float w0 = w2s[col], w1 = w2s[col + 1];
            float v0 = fmaxf(c[ma][na][0], 0.f), v1 = fmaxf(c[ma][na][1], 0.f);
            float v2 = fmaxf(c[ma][na][2], 0.f), v3 = fmaxf(c[ma][na][3], 0.f);
            part[ma][0] += v0 * w0 + v1 * w1;
            part[ma][1] += v2 * w0 + v3 * w1;
        }
    #pragma unroll
    for (int ma = 0; ma < 2; ma++)
        #pragma unroll
        for (int rr = 0; rr < 2; rr++) {
            float v = part[ma][rr];
            v += __shfl_xor_sync(0xffffffffu, v, 1);
            v += __shfl_xor_sync(0xffffffffu, v, 2);
            part[ma][rr] = v;
        }
    if (tig == 0) {
        int nb = wi >> 1;
        #pragma unroll
        for (int ma = 0; ma < 2; ma++)
            #pragma unroll
            for (int rr = 0; rr < 2; rr++) {
                int row = mBlk + ma * 16 + grp + 8 * rr;
                sred[row * 4 + nb] = part[ma][rr];
            }
    }
    __syncthreads();
    if (tid < TP) {
        int p = pb + tid;
        if (p < P) {
            float s = sred[tid * 4] + sred[tid * 4 + 1] +
                      sred[tid * 4 + 2] + sred[tid * 4 + 3];
            d_scores[p] = s + __ldg(b2) + ms[s_si[tid]] + ms[s_sj[tid]];
        }
    }
}

// ---------------------------------------------------------------------------
// Ragged softmax (+epsilon logit 0), one warp per mention
// ---------------------------------------------------------------------------
__global__ void softmax_k(float* __restrict__ out, int M) {
    int warp = (blockIdx.x * blockDim.x + threadIdx.x) >> 5;
    int lane = threadIdx.x & 31;
    if (warp >= M) return;
    int s0 = d_starts[warp], s1 = d_starts[warp + 1];
    int n = s1 - s0;

    float mx = 0.0f;
    for (int i = lane; i < n; i += 32) mx = fmaxf(mx, d_scores[s0 + i]);
    #pragma unroll
    for (int off = 16; off; off >>= 1) mx = fmaxf(mx, __shfl_xor_sync(0xffffffffu, mx, off));

    float sum = 0.0f;
    for (int i = lane; i < n; i += 32) sum += expf(d_scores[s0 + i] - mx);
    #pragma unroll
    for (int off = 16; off; off >>= 1) sum += __shfl_xor_sync(0xffffffffu, sum, off);

    float eps = expf(-mx);
    float inv = 1.0f / (sum + eps);
    float* row = out + (warp + 1) * 161;
    for (int i = lane; i < n; i += 32) row[i] = expf(d_scores[s0 + i] - mx) * inv;
    if (lane == 0) row[n] = eps * inv;
}

// ---------------------------------------------------------------------------
extern "C" void kernel_launch(void* const* d_in, const int* in_sizes, int n_in,
                              void* d_out, int out_size) {
    const float* g_i   = (const float*)d_in[0];
    const float* msc   = (const float*)d_in[1];
    const float* de    = (const float*)d_in[2];
    const float* ge    = (const float*)d_in[3];
    const float* se    = (const float*)d_in[4];
    const float* W1    = (const float*)d_in[5];
    const float* b1    = (const float*)d_in[6];
    const float* W2    = (const float*)d_in[7];
    const float* b2    = (const float*)d_in[8];
    const int*   mids  = (const int*)d_in[9];
    const int*   aids  = (const int*)d_in[10];
    const int*   dists = (const int*)d_in[11];
    const int*   gens  = (const int*)d_in[12];
    const int*   spks  = (const int*)d_in[13];

    int M = in_sizes[1];
    int P = in_sizes[9];
    float* out = (float*)d_out;

    int nWtH  = (480 * 640 / 4 + 255) / 256;   // 300
    int nG16  = (M * 640 / 4 + 255) / 256;
    int fillB = ((out_size + 3) / 4 + 255) / 256;

    cudaFuncSetAttribute(pair_k, cudaFuncAttributeMaxDynamicSharedMemorySize, SM_TOT);
    cudaFuncSetAttribute(abm_k, cudaFuncAttributeMaxDynamicSharedMemorySize, ABM_TOT);

    prep_k<<<nWtH + nG16 + 2 + fillB, 256>>>(out, out_size, de, ge, se, W1, b1,
                                             g_i, mids, P, M, nWtH, nG16);
    abm_k<<<dim3((M + 63) / 64, 2), NT, ABM_TOT>>>(M);
    pair_k<<<(P + TP - 1) / TP, NT, SM_TOT>>>(W2, b2, msc,
                                              mids, aids, dists, gens, spks, P);
    softmax_k<<<(M + 7) / 8, 256>>>(out, M);
}